// round 1
// baseline (speedup 1.0000x reference)
#include <cuda_runtime.h>
#include <cuda_bf16.h>

// Geometry
#define H 512
#define W 512
#define N_ANGLES 512
#define N_DET 736
#define N_SAMP 736

// Padding: sample coords in [-264.3, 775.3] -> pad 272 each side
#define PAD 272
#define PW (W + 2 * PAD)   // 1056
#define PH (H + 2 * PAD)   // 1056

// Quad image: quad[y][x] = (I[y][x], I[y][x+1], I[y+1][x], I[y+1][x+1]) on zero-padded field
__device__ float4 g_quad[PH * PW];

// ---------------------------------------------------------------------------
// Builder: quad[yq][xq] from (x + reco), zero outside image
// ---------------------------------------------------------------------------
__global__ void build_quad_kernel(const float* __restrict__ xin,
                                  const float* __restrict__ rin) {
    int idx = blockIdx.x * blockDim.x + threadIdx.x;
    if (idx >= PH * PW) return;
    int yq = idx / PW;
    int xq = idx - yq * PW;
    int y = yq - PAD;
    int x = xq - PAD;

    float4 q;
    // tap(yy, xx)
    {
        int yy = y, xx = x;
        q.x = (yy >= 0 && yy < H && xx >= 0 && xx < W)
                  ? (xin[yy * W + xx] + rin[yy * W + xx]) : 0.0f;
        xx = x + 1;
        q.y = (yy >= 0 && yy < H && xx >= 0 && xx < W)
                  ? (xin[yy * W + xx] + rin[yy * W + xx]) : 0.0f;
        yy = y + 1; xx = x;
        q.z = (yy >= 0 && yy < H && xx >= 0 && xx < W)
                  ? (xin[yy * W + xx] + rin[yy * W + xx]) : 0.0f;
        xx = x + 1;
        q.w = (yy >= 0 && yy < H && xx >= 0 && xx < W)
                  ? (xin[yy * W + xx] + rin[yy * W + xx]) : 0.0f;
    }
    g_quad[idx] = q;
}

// ---------------------------------------------------------------------------
// reco pass-through copy (vectorized)
// ---------------------------------------------------------------------------
__global__ void copy_reco_kernel(const float4* __restrict__ src,
                                 float4* __restrict__ dst, int n4) {
    int i = blockIdx.x * blockDim.x + threadIdx.x;
    if (i < n4) dst[i] = src[i];
}

// ---------------------------------------------------------------------------
// Projection kernel.
//   grid = (23, 512): blockIdx.y = angle, blockIdx.x = detector block (32 d)
//   block = 256 threads = 8 warps; each warp handles 4 detectors.
//   Lane layout: lane = tq*4 + dq, tq in [0,8), dq in [0,4).
//   Each lane sweeps t = 8*it + tq, it in [0, 92); reduce over tq at the end.
// ---------------------------------------------------------------------------
__global__ void __launch_bounds__(256, 4)
project_kernel(const float* __restrict__ angles, float* __restrict__ sino) {
    const int lane = threadIdx.x & 31;
    const int warp = threadIdx.x >> 5;
    const int tq = lane >> 2;    // 0..7
    const int dq = lane & 3;     // 0..3

    const int angle = blockIdx.y;
    const int d = blockIdx.x * 32 + warp * 4 + dq;

    const float theta = __ldg(&angles[angle]);
    float si, c;
    sincosf(theta, &si, &c);

    const float s = (float)d - 367.5f;                 // (N_DET-1)/2
    const float t0 = (float)tq - 367.5f;               // (N_SAMP-1)/2
    const float ctr = 255.5f + (float)PAD;             // 527.5

    float px = s * c - t0 * si + ctr;
    float py = s * si + t0 * c + ctr;
    const float dx = -8.0f * si;
    const float dy = 8.0f * c;

    float acc = 0.0f;

#pragma unroll 4
    for (int it = 0; it < N_SAMP / 8; ++it) {
        const int xi = __float2int_rd(px);
        const int yi = __float2int_rd(py);
        const float fx = px - (float)xi;
        const float fy = py - (float)yi;
        const float4 q = __ldg(&g_quad[yi * PW + xi]);
        const float top = q.x + fx * (q.y - q.x);
        const float bot = q.z + fx * (q.w - q.z);
        acc += top + fy * (bot - top);
        px += dx;
        py += dy;
    }

    // reduce across tq (lanes separated by multiples of 4)
    acc += __shfl_xor_sync(0xFFFFFFFFu, acc, 16);
    acc += __shfl_xor_sync(0xFFFFFFFFu, acc, 8);
    acc += __shfl_xor_sync(0xFFFFFFFFu, acc, 4);

    if (tq == 0) {
        sino[angle * N_DET + d] = acc;   // STEP = 1.0
    }
}

// ---------------------------------------------------------------------------
extern "C" void kernel_launch(void* const* d_in, const int* in_sizes, int n_in,
                              void* d_out, int out_size) {
    const float* xin    = (const float*)d_in[0];   // [1,512,512]
    const float* rin    = (const float*)d_in[1];   // [1,512,512]
    const float* angles = (const float*)d_in[2];   // [512]

    float* out = (float*)d_out;
    float* sino_out = out;                         // [1,512,736] = 376832 floats
    float* reco_out = out + N_ANGLES * N_DET;      // [1,512,512] = 262144 floats

    // 1) build padded quad image from x + reco
    {
        int total = PH * PW;
        int threads = 256;
        int blocks = (total + threads - 1) / threads;
        build_quad_kernel<<<blocks, threads>>>(xin, rin);
    }

    // 2) copy reco to output tail
    {
        int n4 = (H * W) / 4;
        int threads = 256;
        int blocks = (n4 + threads - 1) / threads;
        copy_reco_kernel<<<blocks, threads>>>((const float4*)rin, (float4*)reco_out, n4);
    }

    // 3) projection
    {
        dim3 grid(N_DET / 32, N_ANGLES);   // (23, 512)
        project_kernel<<<grid, 256>>>(angles, sino_out);
    }
}